// round 9
// baseline (speedup 1.0000x reference)
#include <cuda_runtime.h>
#include <cuda_bf16.h>
#include <cuda_fp8.h>
#include <cmath>
#include <cstdint>

typedef __nv_bfloat16 bf16;

#define C_DIM   512
#define NTOK    4096
#define BATCH   4
#define M_TOT   (BATCH*NTOK)   // 16384
#define GROUPS  32
#define CG      (C_DIM/GROUPS) // 16

#define BM 128
#define BN 128
#define BK 64            // in "elements" (bf16) or "fp8-pairs" (fp8) — 128B rows either way
#define NSTAGE 3

// ---------------- scratch ----------------
__device__ bf16    g_hn   [(size_t)M_TOT*C_DIM];
__device__ uint8_t g_qkv8 [(size_t)M_TOT*3*C_DIM];     // q,k,v in e4m3
__device__ uint8_t g_vt8  [(size_t)BATCH*C_DIM*NTOK];  // V^T per batch [C, NTOK] e4m3
__device__ bf16    g_o    [(size_t)M_TOT*C_DIM];
__device__ bf16    g_wqkvT[3*C_DIM*C_DIM];
__device__ bf16    g_woT  [C_DIM*C_DIM];
__device__ float   g_bqkv [3*C_DIM];
__device__ uint8_t g_E8   [(size_t)BATCH*NTOK*NTOK];   // exp(scores) e4m3
__device__ float   g_psum [(size_t)BATCH*NTOK*32];
__device__ float   g_mean[BATCH*GROUPS];
__device__ float   g_rstd[BATCH*GROUPS];

// ---------------- PTX helpers ----------------
__device__ __forceinline__ uint32_t smem_u32(const void* p) {
    return (uint32_t)__cvta_generic_to_shared(p);
}
__device__ __forceinline__ void cp_async16(uint32_t dst, const void* src) {
    asm volatile("cp.async.cg.shared.global [%0], [%1], 16;\n" :: "r"(dst), "l"(src));
}
__device__ __forceinline__ void cp_commit() { asm volatile("cp.async.commit_group;\n"); }
template<int N>
__device__ __forceinline__ void cp_wait() { asm volatile("cp.async.wait_group %0;\n" :: "n"(N)); }
__device__ __forceinline__ void ldsm4(uint32_t& r0, uint32_t& r1, uint32_t& r2, uint32_t& r3, uint32_t a) {
    asm volatile("ldmatrix.sync.aligned.m8n8.x4.shared.b16 {%0,%1,%2,%3}, [%4];\n"
        : "=r"(r0), "=r"(r1), "=r"(r2), "=r"(r3) : "r"(a));
}
__device__ __forceinline__ void mma16816(float* d, const uint32_t* a, const uint32_t* b) {
    asm volatile(
        "mma.sync.aligned.m16n8k16.row.col.f32.bf16.bf16.f32 "
        "{%0,%1,%2,%3}, {%4,%5,%6,%7}, {%8,%9}, {%0,%1,%2,%3};\n"
        : "+f"(d[0]), "+f"(d[1]), "+f"(d[2]), "+f"(d[3])
        : "r"(a[0]), "r"(a[1]), "r"(a[2]), "r"(a[3]), "r"(b[0]), "r"(b[1]));
}
__device__ __forceinline__ void mma16832f8(float* d, const uint32_t* a, const uint32_t* b) {
    asm volatile(
        "mma.sync.aligned.m16n8k32.row.col.f32.e4m3.e4m3.f32 "
        "{%0,%1,%2,%3}, {%4,%5,%6,%7}, {%8,%9}, {%0,%1,%2,%3};\n"
        : "+f"(d[0]), "+f"(d[1]), "+f"(d[2]), "+f"(d[3])
        : "r"(a[0]), "r"(a[1]), "r"(a[2]), "r"(a[3]), "r"(b[0]), "r"(b[1]));
}

// ---------------- GroupNorm stats ----------------
__global__ void gn_stats_kernel(const float* __restrict__ x) {
    int bg = blockIdx.x;
    int b = bg / GROUPS, g = bg % GROUPS;
    const float* base = x + (size_t)b*NTOK*C_DIM + g*CG;
    float s = 0.f, s2 = 0.f;
    for (int i = threadIdx.x; i < NTOK*(CG/4); i += blockDim.x) {
        int n = i >> 2, q4 = i & 3;
        float4 v = *(const float4*)(base + (size_t)n*C_DIM + q4*4);
        s  += v.x + v.y + v.z + v.w;
        s2 += v.x*v.x + v.y*v.y + v.z*v.z + v.w*v.w;
    }
    __shared__ float sh[256], sh2[256];
    sh[threadIdx.x] = s; sh2[threadIdx.x] = s2;
    __syncthreads();
    for (int off = 128; off > 0; off >>= 1) {
        if (threadIdx.x < off) {
            sh [threadIdx.x] += sh [threadIdx.x + off];
            sh2[threadIdx.x] += sh2[threadIdx.x + off];
        }
        __syncthreads();
    }
    if (threadIdx.x == 0) {
        float inv = 1.0f / (float)(NTOK * CG);
        float m   = sh[0] * inv;
        float var = sh2[0] * inv - m * m;
        g_mean[bg] = m;
        g_rstd[bg] = rsqrtf(var + 1e-6f);
    }
}

// ---------------- GroupNorm apply -> bf16 ----------------
__global__ void gn_apply_kernel(const float* __restrict__ x,
                                const float* __restrict__ scale,
                                const float* __restrict__ bias) {
    int idx = blockIdx.x * blockDim.x + threadIdx.x;
    if (idx >= M_TOT * (C_DIM/4)) return;
    int c4  = idx % (C_DIM/4);
    int row = idx / (C_DIM/4);
    int b   = row / NTOK;
    int c   = c4 * 4;
    int g   = c / CG;
    float m = g_mean[b*GROUPS + g];
    float r = g_rstd[b*GROUPS + g];
    float4 xv = *(const float4*)(x + (size_t)idx*4);
    float4 sv = *(const float4*)(scale + c);
    float4 bv = *(const float4*)(bias  + c);
    float o0 = (xv.x - m) * r * sv.x + bv.x;
    float o1 = (xv.y - m) * r * sv.y + bv.y;
    float o2 = (xv.z - m) * r * sv.z + bv.z;
    float o3 = (xv.w - m) * r * sv.w + bv.w;
    __nv_bfloat162* out = (__nv_bfloat162*)(g_hn + (size_t)idx*4);
    out[0] = __floats2bfloat162_rn(o0, o1);
    out[1] = __floats2bfloat162_rn(o2, o3);
}

// ---------------- fused weight prep ----------------
__global__ void wprep(const float* __restrict__ wq, const float* __restrict__ wk,
                      const float* __restrict__ wv, const float* __restrict__ wo,
                      const float* __restrict__ bq, const float* __restrict__ bk,
                      const float* __restrict__ bv,
                      bf16* __restrict__ wqkvT, bf16* __restrict__ woT,
                      float* __restrict__ bqkv) {
    __shared__ float t[32][33];
    int z = blockIdx.z;
    const float* w = (z == 0) ? wq : (z == 1) ? wk : (z == 2) ? wv : wo;
    bf16* wt = (z < 3) ? (wqkvT + (size_t)z*C_DIM*C_DIM) : woT;
    int k0 = blockIdx.x*32, n0 = blockIdx.y*32;
    int x = threadIdx.x, y = threadIdx.y;
    #pragma unroll
    for (int i = 0; i < 32; i += 8)
        t[y+i][x] = w[(size_t)(k0+y+i)*C_DIM + n0 + x];
    __syncthreads();
    #pragma unroll
    for (int i = 0; i < 32; i += 8)
        wt[(size_t)(n0+y+i)*C_DIM + k0 + x] = __float2bfloat16(t[x][y+i]);
    if (z == 0 && blockIdx.x == 0 && blockIdx.y == 0) {
        int tid = y*32 + x;
        #pragma unroll
        for (int i = 0; i < 2; i++) {
            int c = tid + i*256;
            bqkv[c] = bq[c]; bqkv[C_DIM+c] = bk[c]; bqkv[2*C_DIM+c] = bv[c];
        }
    }
}

// ---------------- V byte-transpose: qkv8 v-section [tok, C] -> vt8 [C, tok] per batch ----------------
__global__ void vtrans8(const uint8_t* __restrict__ qkv8, uint8_t* __restrict__ vt8) {
    __shared__ uint8_t t[64][80];
    int b = blockIdx.z;
    int tok0 = blockIdx.x*64, c0 = blockIdx.y*64;
    int tid = threadIdx.x;                 // 256
    int r = tid >> 2, seg = (tid & 3) * 16;
    const uint8_t* src = qkv8 + ((size_t)(b*NTOK + tok0 + r))*(3*C_DIM) + 2*C_DIM + c0 + seg;
    *(uint4*)&t[r][seg] = *(const uint4*)src;
    __syncthreads();
    uint8_t tmp[16];
    #pragma unroll
    for (int j = 0; j < 16; j++) tmp[j] = t[seg + j][r];
    *(uint4*)(vt8 + (size_t)b*C_DIM*NTOK + (size_t)(c0 + r)*NTOK + tok0 + seg) = *(uint4*)tmp;
}

// ---------------- HMMA/QMMA GEMM ----------------
// C = alpha*(A@B') [+bias] [+resid].  B stored [N,K] row-major (non-trans ldmatrix).
// FP8: A/B pointers are fp8 buffers addressed in PAIR units (lda/ldb/K/sA/sB in pairs);
//      fragment layout identical to bf16, mma op switches to e4m3 m16n8k32.
// OUTT: 0=f32, 1=bf16, 2=fp8(e4m3).  EXPE: v=exp(alpha*acc), rowsums->psum.
// RSCALE: rows scaled by 1/rowsum (computed from psum in prologue).
template<int OUTT, bool BIAS, bool RESID, bool EXPE, bool RSCALE, bool FP8>
__global__ __launch_bounds__(256, 2) void tc_gemm(
    const bf16* __restrict__ Ag, const bf16* __restrict__ Bg, void* __restrict__ Cg,
    int lda, int ldb, int ldc, int K, float alpha,
    const float* __restrict__ bias, const float* __restrict__ resid,
    float* __restrict__ psum,
    size_t sA, size_t sB, size_t sC)
{
    constexpr int APITCH = BK + 8;    // 72 units (144B) — 16B-aligned chunks preserved
    constexpr int BPITCH = BK + 8;
    constexpr int ATILE  = BM * APITCH;
    constexpr int BTILE  = BN * BPITCH;
    extern __shared__ char sm[];
    bf16*  As  = (bf16*)sm;
    bf16*  Bst = (bf16*)(sm + NSTAGE*ATILE*2);
    float* red = (float*)(sm + NSTAGE*(ATILE + BTILE)*2);

    int tid = threadIdx.x, lane = tid & 31, w = tid >> 5;
    int bm = blockIdx.y * BM, bn = blockIdx.x * BN;
    int warpM = (w & 1) * 64, warpN = (w >> 1) * 32;
    int z = blockIdx.z;

    const bf16* Abase = Ag + (size_t)z * sA + (size_t)bm * lda;
    const bf16* Bbase = Bg + (size_t)z * sB + (size_t)bn * ldb;

    if (RSCALE) {
        if (tid < BM) {
            const float* p = psum + ((size_t)z*NTOK + bm + tid)*32;
            float s = 0.f;
            #pragma unroll
            for (int j = 0; j < 32; j++) s += p[j];
            red[tid] = 1.0f / s;
        }
    }

    float acc[4][4][4];
    #pragma unroll
    for (int mi = 0; mi < 4; mi++)
        #pragma unroll
        for (int ni = 0; ni < 4; ni++)
            #pragma unroll
            for (int t = 0; t < 4; t++) acc[mi][ni][t] = 0.f;

    auto load_tile = [&](int kt) {
        int s = kt % NSTAGE;
        int k0 = kt * BK;
        bf16* Asm = As + s*ATILE;
        bf16* Bsm = Bst + s*BTILE;
        #pragma unroll
        for (int j = 0; j < 4; j++) {
            int id = tid + j*256;
            int r = id >> 3, c = (id & 7) * 8;
            cp_async16(smem_u32(Asm + r*APITCH + c), Abase + (size_t)r*lda + k0 + c);
        }
        #pragma unroll
        for (int j = 0; j < 4; j++) {
            int id = tid + j*256;
            int r = id >> 3, c = (id & 7) * 8;
            cp_async16(smem_u32(Bsm + r*BPITCH + c), Bbase + (size_t)r*ldb + k0 + c);
        }
        cp_commit();
    };

    int KT = K / BK;
    load_tile(0);
    load_tile(1);

    for (int kt = 0; kt < KT; kt++) {
        if (kt + 1 < KT) cp_wait<1>(); else cp_wait<0>();
        __syncthreads();
        int s = kt % NSTAGE;
        bf16* Asm = As + s*ATILE;
        bf16* Bsm = Bst + s*BTILE;
        #pragma unroll
        for (int ks = 0; ks < 4; ks++) {
            int k16 = ks * 16;
            uint32_t aF[4][4], bF[4][2];
            #pragma unroll
            for (int mi = 0; mi < 4; mi++) {
                uint32_t addr = smem_u32(Asm + (warpM + mi*16 + (lane & 15))*APITCH
                                             + k16 + (lane >> 4)*8);
                ldsm4(aF[mi][0], aF[mi][1], aF[mi][2], aF[mi][3], addr);
            }
            #pragma unroll
            for (int jj = 0; jj < 2; jj++) {
                uint32_t r0, r1, r2, r3;
                uint32_t addr = smem_u32(Bsm + (warpN + jj*16 + (lane & 15))*BPITCH
                                             + k16 + (lane >> 4)*8);
                ldsm4(r0, r1, r2, r3, addr);
                bF[jj*2  ][0] = r0; bF[jj*2  ][1] = r2;
                bF[jj*2+1][0] = r1; bF[jj*2+1][1] = r3;
            }
            if (ks == 0 && kt + 2 < KT) load_tile(kt + 2);
            #pragma unroll
            for (int mi = 0; mi < 4; mi++)
                #pragma unroll
                for (int ni = 0; ni < 4; ni++) {
                    if (FP8) mma16832f8(acc[mi][ni], aF[mi], bF[ni]);
                    else     mma16816  (acc[mi][ni], aF[mi], bF[ni]);
                }
        }
    }

    // ---------------- epilogue ----------------
    int col0 = bn + warpN;
    float rs[4][2];
    if (EXPE) {
        #pragma unroll
        for (int mi = 0; mi < 4; mi++) { rs[mi][0] = 0.f; rs[mi][1] = 0.f; }
    }
    #pragma unroll
    for (int mi = 0; mi < 4; mi++) {
        #pragma unroll
        for (int h = 0; h < 2; h++) {
            int rl = warpM + mi*16 + (lane >> 2) + h*8;
            int rr = bm + rl;
            float rowscale = 1.f;
            if (RSCALE) rowscale = red[rl];
            #pragma unroll
            for (int ni = 0; ni < 4; ni++) {
                int c = col0 + ni*8 + (lane & 3)*2;
                float v0 = acc[mi][ni][h*2+0] * alpha;
                float v1 = acc[mi][ni][h*2+1] * alpha;
                if (EXPE) { v0 = __expf(v0); v1 = __expf(v1); }
                if (BIAS)  { v0 += bias[c]; v1 += bias[c+1]; }
                if (RSCALE){ v0 *= rowscale; v1 *= rowscale; }
                if (RESID) {
                    const float* rp = resid + (size_t)rr*ldc + c;
                    v0 += rp[0]; v1 += rp[1];
                }
                if (OUTT == 2) {
                    uint8_t* C8 = (uint8_t*)Cg + (size_t)z * sC;
                    __nv_fp8x2_storage_t pk = __nv_cvt_float2_to_fp8x2(
                        make_float2(v0, v1), __NV_SATFINITE, __NV_E4M3);
                    *(uint16_t*)(C8 + (size_t)rr*ldc + c) = (uint16_t)pk;
                    if (EXPE) {
                        __half2_raw hb = __nv_cvt_fp8x2_to_halfraw2(pk, __NV_E4M3);
                        rs[mi][h] += __half2float(*(__half*)&hb.x) + __half2float(*(__half*)&hb.y);
                    }
                } else if (OUTT == 1) {
                    bf16* C = (bf16*)Cg + (size_t)z * sC;
                    *(__nv_bfloat162*)(C + (size_t)rr*ldc + c) = __floats2bfloat162_rn(v0, v1);
                } else {
                    float* C = (float*)Cg + (size_t)z * sC;
                    *(float2*)(C + (size_t)rr*ldc + c) = make_float2(v0, v1);
                }
            }
        }
    }
    if (EXPE) {
        #pragma unroll
        for (int mi = 0; mi < 4; mi++)
            #pragma unroll
            for (int h = 0; h < 2; h++) {
                float v = rs[mi][h];
                v += __shfl_xor_sync(0xffffffffu, v, 1);
                v += __shfl_xor_sync(0xffffffffu, v, 2);
                if ((lane & 3) == 0) {
                    int row_local = warpM + mi*16 + h*8 + (lane >> 2);
                    red[row_local*4 + (w >> 1)] = v;
                }
            }
        __syncthreads();
        if (tid < BM) {
            float s = red[tid*4+0] + red[tid*4+1] + red[tid*4+2] + red[tid*4+3];
            psum[((size_t)z*NTOK + bm + tid)*32 + blockIdx.x] = s;
        }
    }
}

#define SMEMSZ (NSTAGE*(BM*(BK+8) + BN*(BK+8))*2 + BM*4*4)

// ---------------- launch ----------------
extern "C" void kernel_launch(void* const* d_in, const int* in_sizes, int n_in,
                              void* d_out, int out_size) {
    const float* x   = (const float*)d_in[0];
    const float* gns = (const float*)d_in[1];
    const float* gnb = (const float*)d_in[2];
    const float* wq  = (const float*)d_in[3];
    const float* bq  = (const float*)d_in[4];
    const float* wk  = (const float*)d_in[5];
    const float* bk  = (const float*)d_in[6];
    const float* wv  = (const float*)d_in[7];
    const float* bv  = (const float*)d_in[8];
    const float* wo  = (const float*)d_in[9];
    const float* bo  = (const float*)d_in[10];
    float* out = (float*)d_out;

    bf16 *hn, *o, *wqkvT, *woT;
    uint8_t *qkv8, *vt8, *E8;
    float *bqkv, *psum;
    cudaGetSymbolAddress((void**)&hn,    g_hn);
    cudaGetSymbolAddress((void**)&qkv8,  g_qkv8);
    cudaGetSymbolAddress((void**)&vt8,   g_vt8);
    cudaGetSymbolAddress((void**)&o,     g_o);
    cudaGetSymbolAddress((void**)&E8,    g_E8);
    cudaGetSymbolAddress((void**)&wqkvT, g_wqkvT);
    cudaGetSymbolAddress((void**)&woT,   g_woT);
    cudaGetSymbolAddress((void**)&bqkv,  g_bqkv);
    cudaGetSymbolAddress((void**)&psum,  g_psum);

    cudaFuncSetAttribute(tc_gemm<2,true,false,false,false,false>,
                         cudaFuncAttributeMaxDynamicSharedMemorySize, SMEMSZ);
    cudaFuncSetAttribute(tc_gemm<2,false,false,true,false,true>,
                         cudaFuncAttributeMaxDynamicSharedMemorySize, SMEMSZ);
    cudaFuncSetAttribute(tc_gemm<1,false,false,false,true,true>,
                         cudaFuncAttributeMaxDynamicSharedMemorySize, SMEMSZ);
    cudaFuncSetAttribute(tc_gemm<0,true,true,false,false,false>,
                         cudaFuncAttributeMaxDynamicSharedMemorySize, SMEMSZ);

    gn_stats_kernel<<<BATCH*GROUPS, 256>>>(x);                                   // 1
    gn_apply_kernel<<<(M_TOT*(C_DIM/4) + 255)/256, 256>>>(x, gns, gnb);          // 2
    wprep<<<dim3(16, 16, 4), dim3(32, 8)>>>(wq, wk, wv, wo, bq, bk, bv,
                                            wqkvT, woT, bqkv);                   // 3

    // qkv projection (bf16 in, fp8 out): hn @ wqkvT' + bqkv -> qkv8 [M, 1536] e4m3
    tc_gemm<2,true,false,false,false,false><<<dim3(3*C_DIM/BN, M_TOT/BM, 1), 256, SMEMSZ>>>(
        hn, wqkvT, qkv8, C_DIM, C_DIM, 3*C_DIM, C_DIM, 1.f,
        bqkv, nullptr, nullptr, 0, 0, 0);                                        // 4

    float alpha = 1.0f / sqrtf((float)C_DIM);
    // pair-unit geometry for fp8 GEMMs
    int   ldqkv_p = (3*C_DIM)/2;                 // 768 pairs
    size_t sRow_p = (size_t)NTOK * ldqkv_p;
    size_t sS8    = (size_t)NTOK * NTOK;         // fp8 elems

    // E8 = exp(alpha * q8 @ k8^T) e4m3 + per-tile rowsums  (fp8 QMMA)
    tc_gemm<2,false,false,true,false,true><<<dim3(NTOK/BN, NTOK/BM, BATCH), 256, SMEMSZ>>>(
        (const bf16*)qkv8, (const bf16*)(qkv8 + C_DIM), E8,
        ldqkv_p, ldqkv_p, NTOK, C_DIM/2, alpha,
        nullptr, nullptr, psum, sRow_p, sRow_p, sS8);                            // 5 <- ncu

    vtrans8<<<dim3(NTOK/64, C_DIM/64, BATCH), 256>>>(qkv8, vt8);                 // 6

    // o = diag(1/rowsum) * (E8 @ vt8^T)  (fp8 QMMA, bf16 out)
    tc_gemm<1,false,false,false,true,true><<<dim3(C_DIM/BN, NTOK/BM, BATCH), 256, SMEMSZ>>>(
        (const bf16*)E8, (const bf16*)vt8, o,
        NTOK/2, NTOK/2, C_DIM, NTOK/2, 1.f,
        nullptr, nullptr, psum, (size_t)NTOK*NTOK/2, (size_t)C_DIM*NTOK/2,
        (size_t)NTOK*C_DIM);                                                     // 7

    // out = o @ woT' + bo + x  (bf16 HMMA, fp32 out)
    tc_gemm<0,true,true,false,false,false><<<dim3(C_DIM/BN, M_TOT/BM, 1), 256, SMEMSZ>>>(
        o, woT, out, C_DIM, C_DIM, C_DIM, C_DIM, 1.f,
        bo, x, nullptr, 0, 0, 0);                                                // 8
}

// round 11
// speedup vs baseline: 1.2069x; 1.2069x over previous
#include <cuda_runtime.h>
#include <cuda.h>
#include <cuda_bf16.h>
#include <cmath>
#include <cstdint>
#include <cstdio>

typedef __nv_bfloat16 bf16;

#define C_DIM   512
#define NTOK    4096
#define BATCH   4
#define M_TOT   (BATCH*NTOK)   // 16384
#define GROUPS  32
#define CG      (C_DIM/GROUPS) // 16

#define BM 128
#define BN 128
#define BK 64                  // 64 bf16 = 128B rows (SW128 atom)
#define NSTAGE 3
#define TILE_BYTES (BM*128)    // 16384 per operand tile
#define SMEM_ALLOC (4096 + 2*NSTAGE*TILE_BYTES + 1024)   // 103424

// ---------------- scratch ----------------
__device__ bf16  g_hn   [(size_t)M_TOT*C_DIM];
__device__ bf16  g_qkv  [(size_t)M_TOT*3*C_DIM];
__device__ bf16  g_vt   [(size_t)BATCH*C_DIM*NTOK];   // V^T per batch [C, NTOK]
__device__ bf16  g_o    [(size_t)M_TOT*C_DIM];
__device__ bf16  g_wqkvT[3*C_DIM*C_DIM];
__device__ bf16  g_woT  [C_DIM*C_DIM];
__device__ float g_bqkv [3*C_DIM];
__device__ bf16  g_E    [(size_t)BATCH*NTOK*NTOK];
__device__ float g_psum [(size_t)BATCH*NTOK*32];
__device__ float g_mean[BATCH*GROUPS];
__device__ float g_rstd[BATCH*GROUPS];

// ---------------- PTX helpers ----------------
__device__ __forceinline__ uint32_t smem_u32(const void* p) {
    return (uint32_t)__cvta_generic_to_shared(p);
}
__device__ __forceinline__ uint32_t elect_one_pred() {
    uint32_t pred;
    asm volatile("{\n\t.reg .pred p;\n\telect.sync _|p, 0xFFFFFFFF;\n\tselp.b32 %0, 1, 0, p;\n\t}"
        : "=r"(pred));
    return pred;
}
#define MBARRIER_INIT(a, c) \
    asm volatile("mbarrier.init.shared.b64 [%0], %1;" :: "r"((uint32_t)(a)), "r"((uint32_t)(c)) : "memory")
#define MBARRIER_ARRIVE(a) \
    asm volatile("mbarrier.arrive.shared.b64 _, [%0];" :: "r"((uint32_t)(a)) : "memory")
#define MBARRIER_EXPECT_TX(a, b) \
    asm volatile("mbarrier.arrive.expect_tx.shared.b64 _, [%0], %1;" \
        :: "r"((uint32_t)(a)), "r"((uint32_t)(b)) : "memory")
#define MBARRIER_WAIT_PARITY(mb, pp) do { \
    uint32_t _mbar = (uint32_t)(mb); \
    uint32_t _parity = (uint32_t)(pp); \
    uint32_t _done; \
    asm volatile("{\n\t.reg .pred p;\n\t" \
        "mbarrier.try_wait.parity.acquire.cta.shared::cta.b64 p, [%1], %2;\n\t" \
        "selp.b32 %0, 1, 0, p;\n\t}" : "=r"(_done) : "r"(_mbar), "r"(_parity) : "memory"); \
    if (!_done) { \
        asm volatile("{\n\t.reg .pred P1;\n\t" \
            "WAIT_LOOP_%=:\n\t" \
            "mbarrier.try_wait.parity.acquire.cta.shared::cta.b64 P1, [%0], %1, 0x989680;\n\t" \
            "@P1 bra.uni WAIT_DONE_%=;\n\t" \
            "bra.uni WAIT_LOOP_%=;\n\t" \
            "WAIT_DONE_%=:\n\t}" :: "r"(_mbar), "r"(_parity) : "memory"); \
    } \
} while(0)
__device__ __forceinline__ void tma_load_2d(uint32_t dst, const CUtensorMap* map,
                                            int cx, int cy, uint32_t mbar) {
    asm volatile(
        "cp.async.bulk.tensor.2d.shared::cta.global.tile.mbarrier::complete_tx::bytes "
        "[%0], [%1, {%2, %3}], [%4];"
        :: "r"(dst), "l"(map), "r"(cx), "r"(cy), "r"(mbar) : "memory");
}
__device__ __forceinline__ void ldsm4(uint32_t& r0, uint32_t& r1, uint32_t& r2, uint32_t& r3, uint32_t a) {
    asm volatile("ldmatrix.sync.aligned.m8n8.x4.shared.b16 {%0,%1,%2,%3}, [%4];\n"
        : "=r"(r0), "=r"(r1), "=r"(r2), "=r"(r3) : "r"(a));
}
__device__ __forceinline__ void mma16816(float* d, const uint32_t* a, const uint32_t* b) {
    asm volatile(
        "mma.sync.aligned.m16n8k16.row.col.f32.bf16.bf16.f32 "
        "{%0,%1,%2,%3}, {%4,%5,%6,%7}, {%8,%9}, {%0,%1,%2,%3};\n"
        : "+f"(d[0]), "+f"(d[1]), "+f"(d[2]), "+f"(d[3])
        : "r"(a[0]), "r"(a[1]), "r"(a[2]), "r"(a[3]), "r"(b[0]), "r"(b[1]));
}

// ---------------- GroupNorm stats ----------------
__global__ void gn_stats_kernel(const float* __restrict__ x) {
    int bg = blockIdx.x;
    int b = bg / GROUPS, g = bg % GROUPS;
    const float* base = x + (size_t)b*NTOK*C_DIM + g*CG;
    float s = 0.f, s2 = 0.f;
    for (int i = threadIdx.x; i < NTOK*(CG/4); i += blockDim.x) {
        int n = i >> 2, q4 = i & 3;
        float4 v = *(const float4*)(base + (size_t)n*C_DIM + q4*4);
        s  += v.x + v.y + v.z + v.w;
        s2 += v.x*v.x + v.y*v.y + v.z*v.z + v.w*v.w;
    }
    __shared__ float sh[256], sh2[256];
    sh[threadIdx.x] = s; sh2[threadIdx.x] = s2;
    __syncthreads();
    for (int off = 128; off > 0; off >>= 1) {
        if (threadIdx.x < off) {
            sh [threadIdx.x] += sh [threadIdx.x + off];
            sh2[threadIdx.x] += sh2[threadIdx.x + off];
        }
        __syncthreads();
    }
    if (threadIdx.x == 0) {
        float inv = 1.0f / (float)(NTOK * CG);
        float m   = sh[0] * inv;
        float var = sh2[0] * inv - m * m;
        g_mean[bg] = m;
        g_rstd[bg] = rsqrtf(var + 1e-6f);
    }
}

// ---------------- GroupNorm apply -> bf16 ----------------
__global__ void gn_apply_kernel(const float* __restrict__ x,
                                const float* __restrict__ scale,
                                const float* __restrict__ bias) {
    int idx = blockIdx.x * blockDim.x + threadIdx.x;
    if (idx >= M_TOT * (C_DIM/4)) return;
    int c4  = idx % (C_DIM/4);
    int row = idx / (C_DIM/4);
    int b   = row / NTOK;
    int c   = c4 * 4;
    int g   = c / CG;
    float m = g_mean[b*GROUPS + g];
    float r = g_rstd[b*GROUPS + g];
    float4 xv = *(const float4*)(x + (size_t)idx*4);
    float4 sv = *(const float4*)(scale + c);
    float4 bv = *(const float4*)(bias  + c);
    float o0 = (xv.x - m) * r * sv.x + bv.x;
    float o1 = (xv.y - m) * r * sv.y + bv.y;
    float o2 = (xv.z - m) * r * sv.z + bv.z;
    float o3 = (xv.w - m) * r * sv.w + bv.w;
    __nv_bfloat162* out = (__nv_bfloat162*)(g_hn + (size_t)idx*4);
    out[0] = __floats2bfloat162_rn(o0, o1);
    out[1] = __floats2bfloat162_rn(o2, o3);
}

// ---------------- fused weight prep ----------------
__global__ void wprep(const float* __restrict__ wq, const float* __restrict__ wk,
                      const float* __restrict__ wv, const float* __restrict__ wo,
                      const float* __restrict__ bq, const float* __restrict__ bk,
                      const float* __restrict__ bv,
                      bf16* __restrict__ wqkvT, bf16* __restrict__ woT,
                      float* __restrict__ bqkv) {
    __shared__ float t[32][33];
    int z = blockIdx.z;
    const float* w = (z == 0) ? wq : (z == 1) ? wk : (z == 2) ? wv : wo;
    bf16* wt = (z < 3) ? (wqkvT + (size_t)z*C_DIM*C_DIM) : woT;
    int k0 = blockIdx.x*32, n0 = blockIdx.y*32;
    int x = threadIdx.x, y = threadIdx.y;
    #pragma unroll
    for (int i = 0; i < 32; i += 8)
        t[y+i][x] = w[(size_t)(k0+y+i)*C_DIM + n0 + x];
    __syncthreads();
    #pragma unroll
    for (int i = 0; i < 32; i += 8)
        wt[(size_t)(n0+y+i)*C_DIM + k0 + x] = __float2bfloat16(t[x][y+i]);
    if (z == 0 && blockIdx.x == 0 && blockIdx.y == 0) {
        int tid = y*32 + x;
        #pragma unroll
        for (int i = 0; i < 2; i++) {
            int c = tid + i*256;
            bqkv[c] = bq[c]; bqkv[C_DIM+c] = bk[c]; bqkv[2*C_DIM+c] = bv[c];
        }
    }
}

// ---------------- V transpose (bf16): qkv v-section [tok,C] -> vt [C,tok] per batch ----------------
__global__ void vtrans(const bf16* __restrict__ qkv, bf16* __restrict__ vt) {
    __shared__ bf16 t[32][33];
    int b = blockIdx.z;
    const bf16* s = qkv + (size_t)b*NTOK*(3*C_DIM) + 2*C_DIM;
    bf16*       d = vt  + (size_t)b*C_DIM*NTOK;
    int n0 = blockIdx.x*32, c0 = blockIdx.y*32;
    int x = threadIdx.x, y = threadIdx.y;
    #pragma unroll
    for (int i = 0; i < 32; i += 8)
        t[y+i][x] = s[(size_t)(n0+y+i)*(3*C_DIM) + c0 + x];
    __syncthreads();
    #pragma unroll
    for (int i = 0; i < 32; i += 8)
        d[(size_t)(c0+y+i)*NTOK + n0 + x] = t[x][y+i];
}

// ---------------- TMA + mbarrier GEMM ----------------
// C = alpha*(A@B') [+bias] [+resid]. A [M,K] via tmA, B [N,K] via tmB (both SW128, box 64x128).
// OUTT: 0=f32, 1=bf16. EXPE: exp+rowsums->psum. RSCALE: rows scaled by 1/rowsum(psum).
template<int OUTT, bool BIAS, bool RESID, bool EXPE, bool RSCALE>
__global__ __launch_bounds__(256, 2) void tma_gemm(
    const __grid_constant__ CUtensorMap tmA,
    const __grid_constant__ CUtensorMap tmB,
    void* __restrict__ Cg, int ldc, int K, float alpha,
    const float* __restrict__ bias, const float* __restrict__ resid,
    float* __restrict__ psum, int aRowPerZ, int bRowPerZ, size_t sC)
{
    extern __shared__ char dsm[];
    uint32_t raw = smem_u32(dsm);
    uint32_t pad = (1024u - (raw & 1023u)) & 1023u;
    uint32_t sb  = raw + pad;
    char*    sbp = dsm + pad;

    uint32_t fullb  = sb;        // 3 x 8B
    uint32_t emptyb = sb + 24;   // 3 x 8B
    float*   red    = (float*)(sbp + 64);          // 2KB
    uint32_t tA     = sb + 4096;                   // 3 x 16KB
    uint32_t tB     = sb + 4096 + NSTAGE*TILE_BYTES;

    int tid = threadIdx.x, lane = tid & 31, w = tid >> 5;
    int bm = blockIdx.y * BM, bn = blockIdx.x * BN;
    int warpM = (w & 1) * 64, warpN = (w >> 1) * 32;
    int z = blockIdx.z;
    int KT = K / BK;

    if (RSCALE) {
        if (tid < BM) {
            const float* p = psum + ((size_t)z*NTOK + bm + tid)*32;
            float s = 0.f;
            #pragma unroll
            for (int j = 0; j < 32; j++) s += p[j];
            red[tid] = 1.0f / s;
        }
    }

    if (tid == 0) {
        #pragma unroll
        for (int s = 0; s < NSTAGE; s++) {
            MBARRIER_INIT(fullb  + s*8, 1);
            MBARRIER_INIT(emptyb + s*8, 8);
        }
    }
    __syncthreads();

    int ay = z*aRowPerZ + bm, by = z*bRowPerZ + bn;
    if (tid == 0) {
        #pragma unroll
        for (int kt = 0; kt < NSTAGE; kt++) {
            MBARRIER_EXPECT_TX(fullb + kt*8, 2*TILE_BYTES);
            tma_load_2d(tA + kt*TILE_BYTES, &tmA, kt*BK, ay, fullb + kt*8);
            tma_load_2d(tB + kt*TILE_BYTES, &tmB, kt*BK, by, fullb + kt*8);
        }
    }

    // precomputed swizzled-address terms
    uint32_t hi16 = (lane >> 4) * 16;
    uint32_t aOff[4], aXor[4], bOff[2], bXor[2];
    #pragma unroll
    for (int mi = 0; mi < 4; mi++) {
        int r = warpM + mi*16 + (lane & 15);
        aOff[mi] = r * 128;
        aXor[mi] = (r & 7) * 16;
    }
    #pragma unroll
    for (int jj = 0; jj < 2; jj++) {
        int r = warpN + jj*16 + (lane & 15);
        bOff[jj] = r * 128;
        bXor[jj] = (r & 7) * 16;
    }

    float acc[4][4][4];
    #pragma unroll
    for (int mi = 0; mi < 4; mi++)
        #pragma unroll
        for (int ni = 0; ni < 4; ni++)
            #pragma unroll
            for (int t = 0; t < 4; t++) acc[mi][ni][t] = 0.f;

    for (int kt = 0; kt < KT; kt++) {
        int s = kt % NSTAGE, r = kt / NSTAGE;
        MBARRIER_WAIT_PARITY(fullb + s*8, r & 1);
        uint32_t tAs = tA + s*TILE_BYTES, tBs = tB + s*TILE_BYTES;
        #pragma unroll
        for (int ks = 0; ks < 4; ks++) {
            uint32_t cb = ks*32 + hi16;
            uint32_t aF[4][4], bF[4][2];
            #pragma unroll
            for (int mi = 0; mi < 4; mi++)
                ldsm4(aF[mi][0], aF[mi][1], aF[mi][2], aF[mi][3],
                      tAs + aOff[mi] + (cb ^ aXor[mi]));
            #pragma unroll
            for (int jj = 0; jj < 2; jj++) {
                uint32_t r0, r1, r2, r3;
                ldsm4(r0, r1, r2, r3, tBs + bOff[jj] + (cb ^ bXor[jj]));
                bF[jj*2  ][0] = r0; bF[jj*2  ][1] = r2;
                bF[jj*2+1][0] = r1; bF[jj*2+1][1] = r3;
            }
            #pragma unroll
            for (int mi = 0; mi < 4; mi++)
                #pragma unroll
                for (int ni = 0; ni < 4; ni++)
                    mma16816(acc[mi][ni], aF[mi], bF[ni]);
        }
        if (elect_one_pred()) MBARRIER_ARRIVE(emptyb + s*8);
        if (tid == 0 && kt + NSTAGE < KT) {
            MBARRIER_WAIT_PARITY(emptyb + s*8, r & 1);
            MBARRIER_EXPECT_TX(fullb + s*8, 2*TILE_BYTES);
            tma_load_2d(tA + s*TILE_BYTES, &tmA, (kt + NSTAGE)*BK, ay, fullb + s*8);
            tma_load_2d(tB + s*TILE_BYTES, &tmB, (kt + NSTAGE)*BK, by, fullb + s*8);
        }
    }

    // ---------------- epilogue ----------------
    int col0 = bn + warpN;
    float rs[4][2];
    if (EXPE) {
        #pragma unroll
        for (int mi = 0; mi < 4; mi++) { rs[mi][0] = 0.f; rs[mi][1] = 0.f; }
    }
    #pragma unroll
    for (int mi = 0; mi < 4; mi++) {
        #pragma unroll
        for (int h = 0; h < 2; h++) {
            int rl = warpM + mi*16 + (lane >> 2) + h*8;
            int rr = bm + rl;
            float rowscale = 1.f;
            if (RSCALE) rowscale = red[rl];
            #pragma unroll
            for (int ni = 0; ni < 4; ni++) {
                int c = col0 + ni*8 + (lane & 3)*2;
                float v0 = acc[mi][ni][h*2+0] * alpha;
                float v1 = acc[mi][ni][h*2+1] * alpha;
                if (EXPE) { v0 = __expf(v0); v1 = __expf(v1); }
                if (BIAS)  { v0 += bias[c]; v1 += bias[c+1]; }
                if (RSCALE){ v0 *= rowscale; v1 *= rowscale; }
                if (RESID) {
                    const float* rp = resid + (size_t)rr*ldc + c;
                    v0 += rp[0]; v1 += rp[1];
                }
                if (OUTT == 1) {
                    bf16* C = (bf16*)Cg + (size_t)z * sC;
                    __nv_bfloat162 pk = __floats2bfloat162_rn(v0, v1);
                    *(__nv_bfloat162*)(C + (size_t)rr*ldc + c) = pk;
                    if (EXPE) rs[mi][h] += __bfloat162float(pk.x) + __bfloat162float(pk.y);
                } else {
                    float* C = (float*)Cg + (size_t)z * sC;
                    *(float2*)(C + (size_t)rr*ldc + c) = make_float2(v0, v1);
                }
            }
        }
    }
    if (EXPE) {
        #pragma unroll
        for (int mi = 0; mi < 4; mi++)
            #pragma unroll
            for (int h = 0; h < 2; h++) {
                float v = rs[mi][h];
                v += __shfl_xor_sync(0xffffffffu, v, 1);
                v += __shfl_xor_sync(0xffffffffu, v, 2);
                if ((lane & 3) == 0) {
                    int row_local = warpM + mi*16 + h*8 + (lane >> 2);
                    red[row_local*4 + (w >> 1)] = v;
                }
            }
        __syncthreads();
        if (tid < BM) {
            float s = red[tid*4+0] + red[tid*4+1] + red[tid*4+2] + red[tid*4+3];
            psum[((size_t)z*NTOK + bm + tid)*32 + blockIdx.x] = s;
        }
    }
}

// ---------------- host: tensormap encoding ----------------
typedef CUresult (*EncFn)(CUtensorMap*, CUtensorMapDataType, cuuint32_t, void*,
                          const cuuint64_t*, const cuuint64_t*, const cuuint32_t*,
                          const cuuint32_t*, CUtensorMapInterleave, CUtensorMapSwizzle,
                          CUtensorMapL2promotion, CUtensorMapFloatOOBfill);
static EncFn get_encoder() {
    static EncFn fn = nullptr;
    if (!fn) {
        cudaDriverEntryPointQueryResult qr;
        void* p = nullptr;
        cudaGetDriverEntryPointByVersion("cuTensorMapEncodeTiled", &p, 12000,
                                         cudaEnableDefault, &qr);
        fn = (EncFn)p;
    }
    return fn;
}
static void make_map(CUtensorMap* m, void* base, uint64_t inner, uint64_t rows,
                     uint64_t stride_bytes) {
    cuuint64_t dims[2]    = {inner, rows};
    cuuint64_t strides[1] = {stride_bytes};
    cuuint32_t box[2]     = {64, 128};
    cuuint32_t es[2]      = {1, 1};
    get_encoder()(m, CU_TENSOR_MAP_DATA_TYPE_BFLOAT16, 2, base, dims, strides, box, es,
                  CU_TENSOR_MAP_INTERLEAVE_NONE, CU_TENSOR_MAP_SWIZZLE_128B,
                  CU_TENSOR_MAP_L2_PROMOTION_L2_128B, CU_TENSOR_MAP_FLOAT_OOB_FILL_NONE);
}

// ---------------- launch ----------------
extern "C" void kernel_launch(void* const* d_in, const int* in_sizes, int n_in,
                              void* d_out, int out_size) {
    const float* x   = (const float*)d_in[0];
    const float* gns = (const float*)d_in[1];
    const float* gnb = (const float*)d_in[2];
    const float* wq  = (const float*)d_in[3];
    const float* bq  = (const float*)d_in[4];
    const float* wk  = (const float*)d_in[5];
    const float* bk  = (const float*)d_in[6];
    const float* wv  = (const float*)d_in[7];
    const float* bv  = (const float*)d_in[8];
    const float* wo  = (const float*)d_in[9];
    const float* bo  = (const float*)d_in[10];
    float* out = (float*)d_out;

    bf16 *hn, *qkv, *vt, *o, *E, *wqkvT, *woT;
    float *bqkv, *psum;
    cudaGetSymbolAddress((void**)&hn,    g_hn);
    cudaGetSymbolAddress((void**)&qkv,   g_qkv);
    cudaGetSymbolAddress((void**)&vt,    g_vt);
    cudaGetSymbolAddress((void**)&o,     g_o);
    cudaGetSymbolAddress((void**)&E,     g_E);
    cudaGetSymbolAddress((void**)&wqkvT, g_wqkvT);
    cudaGetSymbolAddress((void**)&woT,   g_woT);
    cudaGetSymbolAddress((void**)&bqkv,  g_bqkv);
    cudaGetSymbolAddress((void**)&psum,  g_psum);

    cudaFuncSetAttribute(tma_gemm<1,true,false,false,false>,
                         cudaFuncAttributeMaxDynamicSharedMemorySize, SMEM_ALLOC);
    cudaFuncSetAttribute(tma_gemm<1,false,false,true,false>,
                         cudaFuncAttributeMaxDynamicSharedMemorySize, SMEM_ALLOC);
    cudaFuncSetAttribute(tma_gemm<1,false,false,false,true>,
                         cudaFuncAttributeMaxDynamicSharedMemorySize, SMEM_ALLOC);
    cudaFuncSetAttribute(tma_gemm<0,true,true,false,false>,
                         cudaFuncAttributeMaxDynamicSharedMemorySize, SMEM_ALLOC);

    // tensor maps (built on host at launch/capture time)
    CUtensorMap mHn, mWqkv, mQ, mK, mE, mVt, mO, mWo;
    make_map(&mHn,   hn,          512, 16384, 512*2);
    make_map(&mWqkv, wqkvT,       512, 1536,  512*2);
    make_map(&mQ,    qkv,         512, 16384, 1536*2);
    make_map(&mK,    qkv + C_DIM, 512, 16384, 1536*2);
    make_map(&mE,    E,          4096, 16384, 4096*2);
    make_map(&mVt,   vt,         4096, 2048,  4096*2);
    make_map(&mO,    o,           512, 16384, 512*2);
    make_map(&mWo,   woT,         512, 512,   512*2);

    gn_stats_kernel<<<BATCH*GROUPS, 256>>>(x);                                   // 1
    gn_apply_kernel<<<(M_TOT*(C_DIM/4) + 255)/256, 256>>>(x, gns, gnb);          // 2
    wprep<<<dim3(16, 16, 4), dim3(32, 8)>>>(wq, wk, wv, wo, bq, bk, bv,
                                            wqkvT, woT, bqkv);                   // 3

    // qkv projection: hn @ wqkvT' + bqkv -> qkv bf16 [16384, 1536]
    tma_gemm<1,true,false,false,false><<<dim3(12, 128, 1), 256, SMEM_ALLOC>>>(
        mHn, mWqkv, qkv, 3*C_DIM, C_DIM, 1.f, bqkv, nullptr, nullptr,
        0, 0, 0);                                                                // 4

    float alpha = 1.0f / sqrtf((float)C_DIM);

    // E = exp(alpha * q @ k^T) bf16 + per-tile rowsums
    tma_gemm<1,false,false,true,false><<<dim3(32, 32, BATCH), 256, SMEM_ALLOC>>>(
        mQ, mK, E, NTOK, C_DIM, alpha, nullptr, nullptr, psum,
        NTOK, NTOK, (size_t)NTOK*NTOK);                                          // 5 <- ncu

    vtrans<<<dim3(NTOK/32, C_DIM/32, BATCH), dim3(32, 8)>>>(qkv, vt);            // 6

    // o = diag(1/rowsum) * (E @ vt')  bf16
    tma_gemm<1,false,false,false,true><<<dim3(4, 32, BATCH), 256, SMEM_ALLOC>>>(
        mE, mVt, o, C_DIM, NTOK, 1.f, nullptr, nullptr, psum,
        NTOK, C_DIM, (size_t)NTOK*C_DIM);                                        // 7

    // out = o @ woT' + bo + x  (fp32)
    tma_gemm<0,true,true,false,false><<<dim3(4, 128, 1), 256, SMEM_ALLOC>>>(
        mO, mWo, out, C_DIM, C_DIM, 1.f, bo, x, nullptr,
        0, 0, 0);                                                                // 8
}